// round 3
// baseline (speedup 1.0000x reference)
#include <cuda_runtime.h>
#include <cstdint>
#include <cstddef>

#define DINLINE __device__ __forceinline__

static constexpr int MDIM = 4096;
static constexpr int NDIM = 4096;
static constexpr int KDIM = 4096;

static constexpr int BM = 128;
static constexpr int BN = 128;
static constexpr int BK = 128;                 // 128 s8 = one SW128 row
static constexpr int STAGES = 3;
static constexpr int NUM_K_ITERS = KDIM / BK;  // 32
static constexpr int A_TILE_BYTES = BM * BK;   // 16 KB
static constexpr int B_TILE_BYTES = BN * BK;   // 16 KB
static constexpr int STAGE_BYTES = A_TILE_BYTES + B_TILE_BYTES;  // 32 KB
static constexpr int SMEM_BYTES = STAGES * STAGE_BYTES;          // 96 KB

// Scratch (allocation-free rule: __device__ globals)
__device__ __align__(16) int8_t g_a8[(size_t)MDIM * KDIM];    // mat1 as s8 [M,K]
__device__ __align__(16) int8_t g_b8t[(size_t)NDIM * KDIM];   // mat2^T as s8 [N,K]

// ---------------------------------------------------------------- PTX helpers
DINLINE uint32_t smem_u32(const void* p) {
    uint32_t a;
    asm("{ .reg .u64 t; cvta.to.shared.u64 t, %1; cvt.u32.u64 %0, t; }"
        : "=r"(a) : "l"(p));
    return a;
}

DINLINE uint32_t swz128(uint32_t off) { return off ^ ((off >> 3) & 0x70); }

DINLINE void cp16(uint32_t dst, const void* src) {
    asm volatile("cp.async.cg.shared.global [%0], [%1], 16;"
                 :: "r"(dst), "l"(src));
}

DINLINE void ldsm4(uint32_t* r, uint32_t addr) {
    asm volatile(
        "ldmatrix.sync.aligned.m8n8.x4.shared.b16 {%0, %1, %2, %3}, [%4];"
        : "=r"(r[0]), "=r"(r[1]), "=r"(r[2]), "=r"(r[3]) : "r"(addr));
}

DINLINE void mma_s8(int* d, const uint32_t* a, uint32_t b0, uint32_t b1) {
    asm volatile(
        "mma.sync.aligned.m16n8k32.row.col.s32.s8.s8.s32 "
        "{%0, %1, %2, %3}, {%4, %5, %6, %7}, {%8, %9}, {%0, %1, %2, %3};"
        : "+r"(d[0]), "+r"(d[1]), "+r"(d[2]), "+r"(d[3])
        : "r"(a[0]), "r"(a[1]), "r"(a[2]), "r"(a[3]), "r"(b0), "r"(b1));
}

// ---------------------------------------------------------------- converters
// mat1 int32 [M,K] -> s8 [M,K], 4 elems/thread
__global__ void __launch_bounds__(256) conv_a_kernel(const int* __restrict__ a) {
    size_t i = (size_t)blockIdx.x * blockDim.x + threadIdx.x;   // int4 index
    int4 v = reinterpret_cast<const int4*>(a)[i];
    uint32_t packed = (uint32_t)(v.x & 0xff)
                    | ((uint32_t)(v.y & 0xff) << 8)
                    | ((uint32_t)(v.z & 0xff) << 16)
                    | ((uint32_t)(v.w & 0xff) << 24);
    reinterpret_cast<uint32_t*>(g_a8)[i] = packed;
}

// mat2 int32 [K,N] -> s8 transposed [N,K]
__global__ void __launch_bounds__(1024) conv_bt_kernel(const int* __restrict__ b) {
    __shared__ int8_t tile[32][33];
    const int n0 = blockIdx.x * 32;
    const int k0 = blockIdx.y * 32;
    const int tx = threadIdx.x, ty = threadIdx.y;
    tile[ty][tx] = (int8_t)(b[(size_t)(k0 + ty) * NDIM + n0 + tx] & 0xff);
    __syncthreads();
    g_b8t[(size_t)(n0 + ty) * KDIM + k0 + tx] = tile[tx][ty];
}

// ---------------------------------------------------------------- GEMM
// 128x128x128 tiles, 8 warps (4 M x 2 N), warp tile 32x64, mma.m16n8k32.s8
__global__ void __launch_bounds__(256, 2)
gemm_s8_kernel(const int* __restrict__ inp, float* __restrict__ out) {
    extern __shared__ uint8_t smem[];
    const uint32_t tiles = smem_u32(smem);

    const int tid = threadIdx.x;
    const int wid = tid >> 5;
    const int lane = tid & 31;
    const int wm = wid >> 1;      // 0..3  (32-row slices)
    const int wn = wid & 1;       // 0..1  (64-col slices)

    const int m0 = blockIdx.y * BM;
    const int n0 = blockIdx.x * BN;
    const int8_t* __restrict__ aptr = g_a8  + (size_t)m0 * KDIM;
    const int8_t* __restrict__ bptr = g_b8t + (size_t)n0 * KDIM;

    // loader coords: each thread copies 4 A-chunks + 4 B-chunks of 16B
    const int lrow = tid >> 3;             // 0..31 base row
    const int lko  = (tid & 7) << 4;       // byte offset in row

    int acc[2][8][4];
#pragma unroll
    for (int mi = 0; mi < 2; ++mi)
#pragma unroll
        for (int nb = 0; nb < 8; ++nb)
#pragma unroll
            for (int c = 0; c < 4; ++c) acc[mi][nb][c] = 0;

    // prologue: fill STAGES-1 stages
#pragma unroll
    for (int s = 0; s < STAGES - 1; ++s) {
        const uint32_t a_s = tiles + (uint32_t)s * STAGE_BYTES;
        const uint32_t b_s = a_s + A_TILE_BYTES;
        const int kb = s * BK;
#pragma unroll
        for (int t = 0; t < 4; ++t) {
            int row = lrow + t * 32;
            cp16(a_s + swz128((uint32_t)(row * BK + lko)),
                 aptr + (size_t)row * KDIM + kb + lko);
            cp16(b_s + swz128((uint32_t)(row * BK + lko)),
                 bptr + (size_t)row * KDIM + kb + lko);
        }
        asm volatile("cp.async.commit_group;" ::: "memory");
    }

    // precomputed ldmatrix smem offsets (within a stage)
    const uint32_t lm_row = (uint32_t)(lane & 15);
    const uint32_t lm_ch  = (uint32_t)((lane >> 4) << 4);

#pragma unroll 1
    for (int i = 0; i < NUM_K_ITERS; ++i) {
        asm volatile("cp.async.wait_group %0;" :: "n"(STAGES - 2) : "memory");
        __syncthreads();

        const int s = i % STAGES;
        const uint32_t a_s = tiles + (uint32_t)s * STAGE_BYTES;
        const uint32_t b_s = a_s + A_TILE_BYTES;

#pragma unroll
        for (int ks = 0; ks < 4; ++ks) {
            uint32_t afr[2][4], bfr[4][4];
#pragma unroll
            for (int mi = 0; mi < 2; ++mi) {
                uint32_t row = (uint32_t)(wm * 32 + mi * 16) + lm_row;
                ldsm4(afr[mi], a_s + swz128(row * BK + (uint32_t)(ks * 32) + lm_ch));
            }
#pragma unroll
            for (int nf = 0; nf < 4; ++nf) {
                uint32_t row = (uint32_t)(wn * 64 + nf * 16) + lm_row;
                ldsm4(bfr[nf], b_s + swz128(row * BK + (uint32_t)(ks * 32) + lm_ch));
            }
#pragma unroll
            for (int mi = 0; mi < 2; ++mi)
#pragma unroll
                for (int nb = 0; nb < 8; ++nb)
                    mma_s8(acc[mi][nb], afr[mi], bfr[nb >> 1][nb & 1],
                           bfr[nb >> 1][(nb & 1) + 2]);
        }

        // issue next stage
        const int inext = i + STAGES - 1;
        if (inext < NUM_K_ITERS) {
            const int sn = inext % STAGES;
            const uint32_t an = tiles + (uint32_t)sn * STAGE_BYTES;
            const uint32_t bn = an + A_TILE_BYTES;
            const int kb = inext * BK;
#pragma unroll
            for (int t = 0; t < 4; ++t) {
                int row = lrow + t * 32;
                cp16(an + swz128((uint32_t)(row * BK + lko)),
                     aptr + (size_t)row * KDIM + kb + lko);
                cp16(bn + swz128((uint32_t)(row * BK + lko)),
                     bptr + (size_t)row * KDIM + kb + lko);
            }
        }
        asm volatile("cp.async.commit_group;" ::: "memory");
    }

    // ---------------- epilogue: acc + input -> float
    const int rbase = m0 + wm * 32 + (lane >> 2);
    const int cbase = n0 + wn * 64 + ((lane & 3) << 1);
#pragma unroll
    for (int mi = 0; mi < 2; ++mi) {
#pragma unroll
        for (int nb = 0; nb < 8; ++nb) {
            const int col = cbase + nb * 8;
            const int r0 = rbase + mi * 16;
            {
                const size_t idx = (size_t)r0 * NDIM + col;
                int2 iv = *reinterpret_cast<const int2*>(inp + idx);
                float2 f;
                f.x = (float)(acc[mi][nb][0] + iv.x);
                f.y = (float)(acc[mi][nb][1] + iv.y);
                *reinterpret_cast<float2*>(out + idx) = f;
            }
            {
                const size_t idx = (size_t)(r0 + 8) * NDIM + col;
                int2 iv = *reinterpret_cast<const int2*>(inp + idx);
                float2 f;
                f.x = (float)(acc[mi][nb][2] + iv.x);
                f.y = (float)(acc[mi][nb][3] + iv.y);
                *reinterpret_cast<float2*>(out + idx) = f;
            }
        }
    }
}

// ---------------------------------------------------------------- launch
extern "C" void kernel_launch(void* const* d_in, const int* in_sizes, int n_in,
                              void* d_out, int out_size) {
    const int* inp = (const int*)d_in[0];   // input_tensor [M,N] int32
    const int* m1  = (const int*)d_in[1];   // mat1 [M,K] int32
    const int* m2  = (const int*)d_in[2];   // mat2 [K,N] int32
    float* out = (float*)d_out;

    conv_a_kernel<<<(MDIM * KDIM / 4) / 256, 256>>>(m1);
    conv_bt_kernel<<<dim3(NDIM / 32, KDIM / 32), dim3(32, 32)>>>(m2);

    cudaFuncSetAttribute(gemm_s8_kernel,
                         cudaFuncAttributeMaxDynamicSharedMemorySize, SMEM_BYTES);
    gemm_s8_kernel<<<dim3(NDIM / BN, MDIM / BM), 256, SMEM_BYTES>>>(inp, out);
}

// round 5
// speedup vs baseline: 1.0386x; 1.0386x over previous
#include <cuda_runtime.h>
#include <cstdint>
#include <cstddef>

#define DINLINE __device__ __forceinline__

static constexpr int MDIM = 4096;
static constexpr int NDIM = 4096;
static constexpr int KDIM = 4096;

static constexpr int BM = 128;
static constexpr int BN = 256;
static constexpr int BK = 128;                 // 128 s8 = one SW128 row
static constexpr int STAGES = 4;
static constexpr int NUM_K_ITERS = KDIM / BK;  // 32
static constexpr int A_TILE_BYTES = BM * BK;   // 16 KB
static constexpr int B_TILE_BYTES = BN * BK;   // 32 KB
static constexpr int STAGE_BYTES = A_TILE_BYTES + B_TILE_BYTES;  // 48 KB
static constexpr int SMEM_BYTES = STAGES * STAGE_BYTES;          // 192 KB

// Scratch (allocation-free rule: __device__ globals)
__device__ __align__(16) int8_t g_a8[(size_t)MDIM * KDIM];    // mat1 as s8 [M,K]
__device__ __align__(16) int8_t g_b8t[(size_t)NDIM * KDIM];   // mat2^T as s8 [N,K]

// ---------------------------------------------------------------- PTX helpers
DINLINE uint32_t smem_u32(const void* p) {
    uint32_t a;
    asm("{ .reg .u64 t; cvta.to.shared.u64 t, %1; cvt.u32.u64 %0, t; }"
        : "=r"(a) : "l"(p));
    return a;
}

DINLINE uint32_t swz128(uint32_t off) { return off ^ ((off >> 3) & 0x70); }

DINLINE void cp16(uint32_t dst, const void* src) {
    asm volatile("cp.async.cg.shared.global [%0], [%1], 16;"
                 :: "r"(dst), "l"(src));
}

DINLINE void ldsm4(uint32_t* r, uint32_t addr) {
    asm volatile(
        "ldmatrix.sync.aligned.m8n8.x4.shared.b16 {%0, %1, %2, %3}, [%4];"
        : "=r"(r[0]), "=r"(r[1]), "=r"(r[2]), "=r"(r[3]) : "r"(addr));
}

DINLINE void mma_s8(int* d, const uint32_t* a, uint32_t b0, uint32_t b1) {
    asm volatile(
        "mma.sync.aligned.m16n8k32.row.col.s32.s8.s8.s32 "
        "{%0, %1, %2, %3}, {%4, %5, %6, %7}, {%8, %9}, {%0, %1, %2, %3};"
        : "+r"(d[0]), "+r"(d[1]), "+r"(d[2]), "+r"(d[3])
        : "r"(a[0]), "r"(a[1]), "r"(a[2]), "r"(a[3]), "r"(b0), "r"(b1));
}

// ---------------------------------------------------------------- converters
// mat1 int32 [M,K] -> s8 [M,K], 4 elems/thread (near HBM roofline already)
__global__ void __launch_bounds__(256) conv_a_kernel(const int* __restrict__ a) {
    size_t i = (size_t)blockIdx.x * blockDim.x + threadIdx.x;   // int4 index
    int4 v = reinterpret_cast<const int4*>(a)[i];
    uint32_t packed = (uint32_t)(v.x & 0xff)
                    | ((uint32_t)(v.y & 0xff) << 8)
                    | ((uint32_t)(v.z & 0xff) << 16)
                    | ((uint32_t)(v.w & 0xff) << 24);
    reinterpret_cast<uint32_t*>(g_a8)[i] = packed;
}

// mat2 int32 [K,N] -> s8 transposed [N,K]; 64x64 tiles, u32-coalesced stores
__global__ void __launch_bounds__(256) conv_bt_kernel(const int* __restrict__ b) {
    __shared__ int8_t tile[64][68];     // row stride 68 (4-aligned, conflict-light)
    const int n0 = blockIdx.x * 64;
    const int k0 = blockIdx.y * 64;
    const int tid = threadIdx.x;

    const int ln4 = (tid & 15) * 4;     // n offset (4 per thread via int4)
    const int lk  = tid >> 4;           // k row 0..15
#pragma unroll
    for (int p = 0; p < 4; ++p) {
        const int k = lk + p * 16;
        int4 v = *reinterpret_cast<const int4*>(
            &b[(size_t)(k0 + k) * NDIM + n0 + ln4]);
        tile[ln4 + 0][k] = (int8_t)(v.x & 0xff);
        tile[ln4 + 1][k] = (int8_t)(v.y & 0xff);
        tile[ln4 + 2][k] = (int8_t)(v.z & 0xff);
        tile[ln4 + 3][k] = (int8_t)(v.w & 0xff);
    }
    __syncthreads();

    const int sn  = tid >> 4;           // n row 0..15 per pass
    const int sk4 = (tid & 15) * 4;     // k byte offset
#pragma unroll
    for (int p = 0; p < 4; ++p) {
        const int n = sn + p * 16;
        uint32_t w = *reinterpret_cast<const uint32_t*>(&tile[n][sk4]);
        *reinterpret_cast<uint32_t*>(
            &g_b8t[(size_t)(n0 + n) * KDIM + k0 + sk4]) = w;
    }
}

// ---------------------------------------------------------------- GEMM
// 128x256x128 tiles, 8 warps (2 M x 4 N), warp tile 64x64, mma.m16n8k32.s8
__global__ void __launch_bounds__(256, 1)
gemm_s8_kernel(const int* __restrict__ inp, float* __restrict__ out) {
    extern __shared__ uint8_t smem[];
    const uint32_t tiles = smem_u32(smem);

    const int tid = threadIdx.x;
    const int wid = tid >> 5;
    const int lane = tid & 31;
    const int wm = wid >> 2;      // 0..1  (64-row slices)
    const int wn = wid & 3;       // 0..3  (64-col slices)

    const int m0 = blockIdx.y * BM;
    const int n0 = blockIdx.x * BN;
    const int8_t* __restrict__ aptr = g_a8  + (size_t)m0 * KDIM;
    const int8_t* __restrict__ bptr = g_b8t + (size_t)n0 * KDIM;

    // loader coords: each thread copies 4 A-chunks + 8 B-chunks of 16B
    const int lrow = tid >> 3;             // 0..31 base row
    const int lko  = (tid & 7) << 4;       // byte offset in row

    int acc[4][8][4];
#pragma unroll
    for (int mi = 0; mi < 4; ++mi)
#pragma unroll
        for (int nb = 0; nb < 8; ++nb)
#pragma unroll
            for (int c = 0; c < 4; ++c) acc[mi][nb][c] = 0;

    // prologue: fill STAGES-1 stages
#pragma unroll
    for (int s = 0; s < STAGES - 1; ++s) {
        const uint32_t a_s = tiles + (uint32_t)s * STAGE_BYTES;
        const uint32_t b_s = a_s + A_TILE_BYTES;
        const int kb = s * BK;
#pragma unroll
        for (int t = 0; t < 4; ++t) {
            int row = lrow + t * 32;
            cp16(a_s + swz128((uint32_t)(row * BK + lko)),
                 aptr + (size_t)row * KDIM + kb + lko);
        }
#pragma unroll
        for (int t = 0; t < 8; ++t) {
            int row = lrow + t * 32;
            cp16(b_s + swz128((uint32_t)(row * BK + lko)),
                 bptr + (size_t)row * KDIM + kb + lko);
        }
        asm volatile("cp.async.commit_group;" ::: "memory");
    }

    // ldmatrix lane addressing (within a stage)
    const uint32_t lm_row = (uint32_t)(lane & 15);
    const uint32_t lm_ch  = (uint32_t)((lane >> 4) << 4);

#pragma unroll 1
    for (int i = 0; i < NUM_K_ITERS; ++i) {
        asm volatile("cp.async.wait_group %0;" :: "n"(STAGES - 2) : "memory");
        __syncthreads();

        const int s = i % STAGES;
        const uint32_t a_s = tiles + (uint32_t)s * STAGE_BYTES;
        const uint32_t b_s = a_s + A_TILE_BYTES;

#pragma unroll
        for (int ks = 0; ks < 4; ++ks) {
            uint32_t afr[4][4], bfr[4][4];
#pragma unroll
            for (int mi = 0; mi < 4; ++mi) {
                uint32_t row = (uint32_t)(wm * 64 + mi * 16) + lm_row;
                ldsm4(afr[mi], a_s + swz128(row * BK + (uint32_t)(ks * 32) + lm_ch));
            }
#pragma unroll
            for (int nf = 0; nf < 4; ++nf) {
                uint32_t row = (uint32_t)(wn * 64 + nf * 16) + lm_row;
                ldsm4(bfr[nf], b_s + swz128(row * BK + (uint32_t)(ks * 32) + lm_ch));
            }
#pragma unroll
            for (int mi = 0; mi < 4; ++mi)
#pragma unroll
                for (int nb = 0; nb < 8; ++nb)
                    mma_s8(acc[mi][nb], afr[mi], bfr[nb >> 1][nb & 1],
                           bfr[nb >> 1][(nb & 1) + 2]);
        }

        // issue next stage
        const int inext = i + STAGES - 1;
        if (inext < NUM_K_ITERS) {
            const int sn = inext % STAGES;
            const uint32_t an = tiles + (uint32_t)sn * STAGE_BYTES;
            const uint32_t bn = an + A_TILE_BYTES;
            const int kb = inext * BK;
#pragma unroll
            for (int t = 0; t < 4; ++t) {
                int row = lrow + t * 32;
                cp16(an + swz128((uint32_t)(row * BK + lko)),
                     aptr + (size_t)row * KDIM + kb + lko);
            }
#pragma unroll
            for (int t = 0; t < 8; ++t) {
                int row = lrow + t * 32;
                cp16(bn + swz128((uint32_t)(row * BK + lko)),
                     bptr + (size_t)row * KDIM + kb + lko);
            }
        }
        asm volatile("cp.async.commit_group;" ::: "memory");
    }

    // ---------------- epilogue: acc + input -> float
    const int rbase = m0 + wm * 64 + (lane >> 2);
    const int cbase = n0 + wn * 64 + ((lane & 3) << 1);
#pragma unroll
    for (int mi = 0; mi < 4; ++mi) {
#pragma unroll
        for (int nb = 0; nb < 8; ++nb) {
            const int col = cbase + nb * 8;
            const int r0 = rbase + mi * 16;
            {
                const size_t idx = (size_t)r0 * NDIM + col;
                int2 iv = *reinterpret_cast<const int2*>(inp + idx);
                float2 f;
                f.x = (float)(acc[mi][nb][0] + iv.x);
                f.y = (float)(acc[mi][nb][1] + iv.y);
                *reinterpret_cast<float2*>(out + idx) = f;
            }
            {
                const size_t idx = (size_t)(r0 + 8) * NDIM + col;
                int2 iv = *reinterpret_cast<const int2*>(inp + idx);
                float2 f;
                f.x = (float)(acc[mi][nb][2] + iv.x);
                f.y = (float)(acc[mi][nb][3] + iv.y);
                *reinterpret_cast<float2*>(out + idx) = f;
            }
        }
    }
}

// ---------------------------------------------------------------- launch
extern "C" void kernel_launch(void* const* d_in, const int* in_sizes, int n_in,
                              void* d_out, int out_size) {
    const int* inp = (const int*)d_in[0];   // input_tensor [M,N] int32
    const int* m1  = (const int*)d_in[1];   // mat1 [M,K] int32
    const int* m2  = (const int*)d_in[2];   // mat2 [K,N] int32
    float* out = (float*)d_out;

    conv_a_kernel<<<(MDIM * KDIM / 4) / 256, 256>>>(m1);
    conv_bt_kernel<<<dim3(NDIM / 64, KDIM / 64), 256>>>(m2);

    cudaFuncSetAttribute(gemm_s8_kernel,
                         cudaFuncAttributeMaxDynamicSharedMemorySize, SMEM_BYTES);
    gemm_s8_kernel<<<dim3(NDIM / BN, MDIM / BM), 256, SMEM_BYTES>>>(inp, out);
}

// round 7
// speedup vs baseline: 1.2135x; 1.1684x over previous
#include <cuda_runtime.h>
#include <cstdint>
#include <cstddef>

#define DINLINE __device__ __forceinline__

static constexpr int MDIM = 4096;
static constexpr int NDIM = 4096;
static constexpr int KDIM = 4096;

static constexpr int BM = 128;
static constexpr int BN = 128;
static constexpr int BK = 128;                 // 128 s8 = one SW128 row
static constexpr int STAGES = 3;
static constexpr int NUM_K_ITERS = KDIM / BK;  // 32
static constexpr int A_TILE_BYTES = BM * BK;   // 16 KB
static constexpr int B_TILE_BYTES = BN * BK;   // 16 KB
static constexpr int STAGE_BYTES = A_TILE_BYTES + B_TILE_BYTES;  // 32 KB
static constexpr int SMEM_BYTES = STAGES * STAGE_BYTES;          // 96 KB -> 2 CTA/SM

// Scratch (allocation-free rule: __device__ globals)
__device__ __align__(16) int8_t g_a8[(size_t)MDIM * KDIM];    // mat1 as s8 [M,K]
__device__ __align__(16) int8_t g_b8t[(size_t)NDIM * KDIM];   // mat2^T as s8 [N,K]

// ---------------------------------------------------------------- PTX helpers
DINLINE uint32_t smem_u32(const void* p) {
    uint32_t a;
    asm("{ .reg .u64 t; cvta.to.shared.u64 t, %1; cvt.u32.u64 %0, t; }"
        : "=r"(a) : "l"(p));
    return a;
}

DINLINE uint32_t swz128(uint32_t off) { return off ^ ((off >> 3) & 0x70); }

DINLINE void cp16(uint32_t dst, const void* src) {
    asm volatile("cp.async.cg.shared.global [%0], [%1], 16;"
                 :: "r"(dst), "l"(src));
}

DINLINE void ldsm4(uint32_t* r, uint32_t addr) {
    asm volatile(
        "ldmatrix.sync.aligned.m8n8.x4.shared.b16 {%0, %1, %2, %3}, [%4];"
        : "=r"(r[0]), "=r"(r[1]), "=r"(r[2]), "=r"(r[3]) : "r"(addr));
}

DINLINE void mma_s8(int* d, const uint32_t* a, uint32_t b0, uint32_t b1) {
    asm volatile(
        "mma.sync.aligned.m16n8k32.row.col.s32.s8.s8.s32 "
        "{%0, %1, %2, %3}, {%4, %5, %6, %7}, {%8, %9}, {%0, %1, %2, %3};"
        : "+r"(d[0]), "+r"(d[1]), "+r"(d[2]), "+r"(d[3])
        : "r"(a[0]), "r"(a[1]), "r"(a[2]), "r"(a[3]), "r"(b0), "r"(b1));
}

// ---------------------------------------------------------------- fused converter
// blocks [0, CONV_A_BLOCKS)           : mat1 int32 [M,K] -> s8 [M,K]
// blocks [CONV_A_BLOCKS, +CONV_BT_BL) : mat2 int32 [K,N] -> s8^T [N,K]
static constexpr int CONV_A_BLOCKS  = (MDIM * KDIM / 4) / 256;      // 16384
static constexpr int CONV_BT_BLOCKS = (KDIM / 64) * (NDIM / 64);    // 4096

__global__ void __launch_bounds__(256)
conv_fused_kernel(const int* __restrict__ a, const int* __restrict__ b) {
    const int tid = threadIdx.x;
    if (blockIdx.x < CONV_A_BLOCKS) {
        size_t i = (size_t)blockIdx.x * 256 + tid;   // int4 index
        int4 v = reinterpret_cast<const int4*>(a)[i];
        uint32_t packed = (uint32_t)(v.x & 0xff)
                        | ((uint32_t)(v.y & 0xff) << 8)
                        | ((uint32_t)(v.z & 0xff) << 16)
                        | ((uint32_t)(v.w & 0xff) << 24);
        reinterpret_cast<uint32_t*>(g_a8)[i] = packed;
        return;
    }
    __shared__ int8_t tile[64][68];
    const int t64 = blockIdx.x - CONV_A_BLOCKS;
    const int n0 = (t64 & 63) * 64;
    const int k0 = (t64 >> 6) * 64;

    const int ln4 = (tid & 15) * 4;     // n offset (4 per thread via int4)
    const int lk  = tid >> 4;           // k row 0..15
#pragma unroll
    for (int p = 0; p < 4; ++p) {
        const int k = lk + p * 16;
        int4 v = *reinterpret_cast<const int4*>(
            &b[(size_t)(k0 + k) * NDIM + n0 + ln4]);
        tile[ln4 + 0][k] = (int8_t)(v.x & 0xff);
        tile[ln4 + 1][k] = (int8_t)(v.y & 0xff);
        tile[ln4 + 2][k] = (int8_t)(v.z & 0xff);
        tile[ln4 + 3][k] = (int8_t)(v.w & 0xff);
    }
    __syncthreads();

    const int sn  = tid >> 4;           // n row 0..15 per pass
    const int sk4 = (tid & 15) * 4;     // k byte offset
#pragma unroll
    for (int p = 0; p < 4; ++p) {
        const int n = sn + p * 16;
        uint32_t w = *reinterpret_cast<const uint32_t*>(&tile[n][sk4]);
        *reinterpret_cast<uint32_t*>(
            &g_b8t[(size_t)(n0 + n) * KDIM + k0 + sk4]) = w;
    }
}

// ---------------------------------------------------------------- GEMM
// 128x128x128 tiles, 4 warps (2 M x 2 N), warp tile 64x64, 2 CTAs/SM
__global__ void __launch_bounds__(128, 2)
gemm_s8_kernel(const int* __restrict__ inp, float* __restrict__ out) {
    extern __shared__ uint8_t smem[];
    const uint32_t tiles = smem_u32(smem);

    const int tid = threadIdx.x;
    const int wid = tid >> 5;
    const int lane = tid & 31;
    const int wm = wid >> 1;      // 0..1  (64-row slices)
    const int wn = wid & 1;       // 0..1  (64-col slices)

    const int m0 = blockIdx.y * BM;
    const int n0 = blockIdx.x * BN;
    const int8_t* __restrict__ aptr = g_a8  + (size_t)m0 * KDIM;
    const int8_t* __restrict__ bptr = g_b8t + (size_t)n0 * KDIM;

    // loader coords: 128 threads copy 8 A-chunks + 8 B-chunks of 16B each
    const int lrow = tid >> 3;             // 0..15 base row
    const int lko  = (tid & 7) << 4;       // byte offset in row

    int acc[4][8][4];
#pragma unroll
    for (int mi = 0; mi < 4; ++mi)
#pragma unroll
        for (int nb = 0; nb < 8; ++nb)
#pragma unroll
            for (int c = 0; c < 4; ++c) acc[mi][nb][c] = 0;

    // prologue: fill STAGES-1 stages
#pragma unroll
    for (int s = 0; s < STAGES - 1; ++s) {
        const uint32_t a_s = tiles + (uint32_t)s * STAGE_BYTES;
        const uint32_t b_s = a_s + A_TILE_BYTES;
        const int kb = s * BK;
#pragma unroll
        for (int t = 0; t < 8; ++t) {
            int row = lrow + t * 16;
            cp16(a_s + swz128((uint32_t)(row * BK + lko)),
                 aptr + (size_t)row * KDIM + kb + lko);
            cp16(b_s + swz128((uint32_t)(row * BK + lko)),
                 bptr + (size_t)row * KDIM + kb + lko);
        }
        asm volatile("cp.async.commit_group;" ::: "memory");
    }

    // ldmatrix lane addressing (within a stage)
    const uint32_t lm_row = (uint32_t)(lane & 15);
    const uint32_t lm_ch  = (uint32_t)((lane >> 4) << 4);

#pragma unroll 1
    for (int i = 0; i < NUM_K_ITERS; ++i) {
        asm volatile("cp.async.wait_group %0;" :: "n"(STAGES - 2) : "memory");
        __syncthreads();

        const int s = i % STAGES;
        const uint32_t a_s = tiles + (uint32_t)s * STAGE_BYTES;
        const uint32_t b_s = a_s + A_TILE_BYTES;

#pragma unroll
        for (int ks = 0; ks < 4; ++ks) {
            uint32_t afr[4][4], bfr[4][4];
#pragma unroll
            for (int mi = 0; mi < 4; ++mi) {
                uint32_t row = (uint32_t)(wm * 64 + mi * 16) + lm_row;
                ldsm4(afr[mi], a_s + swz128(row * BK + (uint32_t)(ks * 32) + lm_ch));
            }
#pragma unroll
            for (int nf = 0; nf < 4; ++nf) {
                uint32_t row = (uint32_t)(wn * 64 + nf * 16) + lm_row;
                ldsm4(bfr[nf], b_s + swz128(row * BK + (uint32_t)(ks * 32) + lm_ch));
            }
#pragma unroll
            for (int mi = 0; mi < 4; ++mi)
#pragma unroll
                for (int nb = 0; nb < 8; ++nb)
                    mma_s8(acc[mi][nb], afr[mi], bfr[nb >> 1][nb & 1],
                           bfr[nb >> 1][(nb & 1) + 2]);
        }

        // issue next stage
        const int inext = i + STAGES - 1;
        if (inext < NUM_K_ITERS) {
            const int sn = inext % STAGES;
            const uint32_t an = tiles + (uint32_t)sn * STAGE_BYTES;
            const uint32_t bn = an + A_TILE_BYTES;
            const int kb = inext * BK;
#pragma unroll
            for (int t = 0; t < 8; ++t) {
                int row = lrow + t * 16;
                cp16(an + swz128((uint32_t)(row * BK + lko)),
                     aptr + (size_t)row * KDIM + kb + lko);
                cp16(bn + swz128((uint32_t)(row * BK + lko)),
                     bptr + (size_t)row * KDIM + kb + lko);
            }
        }
        asm volatile("cp.async.commit_group;" ::: "memory");
    }

    // ---------------- epilogue: acc + input -> float
    const int rbase = m0 + wm * 64 + (lane >> 2);
    const int cbase = n0 + wn * 64 + ((lane & 3) << 1);
#pragma unroll
    for (int mi = 0; mi < 4; ++mi) {
#pragma unroll
        for (int nb = 0; nb < 8; ++nb) {
            const int col = cbase + nb * 8;
            const int r0 = rbase + mi * 16;
            {
                const size_t idx = (size_t)r0 * NDIM + col;
                int2 iv = *reinterpret_cast<const int2*>(inp + idx);
                float2 f;
                f.x = (float)(acc[mi][nb][0] + iv.x);
                f.y = (float)(acc[mi][nb][1] + iv.y);
                *reinterpret_cast<float2*>(out + idx) = f;
            }
            {
                const size_t idx = (size_t)(r0 + 8) * NDIM + col;
                int2 iv = *reinterpret_cast<const int2*>(inp + idx);
                float2 f;
                f.x = (float)(acc[mi][nb][2] + iv.x);
                f.y = (float)(acc[mi][nb][3] + iv.y);
                *reinterpret_cast<float2*>(out + idx) = f;
            }
        }
    }
}

// ---------------------------------------------------------------- launch
extern "C" void kernel_launch(void* const* d_in, const int* in_sizes, int n_in,
                              void* d_out, int out_size) {
    const int* inp = (const int*)d_in[0];   // input_tensor [M,N] int32
    const int* m1  = (const int*)d_in[1];   // mat1 [M,K] int32
    const int* m2  = (const int*)d_in[2];   // mat2 [K,N] int32
    float* out = (float*)d_out;

    conv_fused_kernel<<<CONV_A_BLOCKS + CONV_BT_BLOCKS, 256>>>(m1, m2);

    cudaFuncSetAttribute(gemm_s8_kernel,
                         cudaFuncAttributeMaxDynamicSharedMemorySize, SMEM_BYTES);
    gemm_s8_kernel<<<dim3(NDIM / BN, MDIM / BM), 128, SMEM_BYTES>>>(inp, out);
}